// round 5
// baseline (speedup 1.0000x reference)
#include <cuda_runtime.h>

#define N_NODES 100000
#define IN_CH   128
#define OUT_TOT 128   // HEADS * OUT_CH
#define N_EDGES 1600000

#define BM 128
#define BN 128
#define BK 32
#define NT 256

typedef unsigned long long ull;

// Per-node "has incoming edge" flag. Zero-initialized at module load;
// the GEMM epilogue re-zeroes it every launch => graph-replay deterministic.
__device__ unsigned char g_mask[N_NODES];

__global__ void mask_scatter_kernel(const int* __restrict__ col) {
    int i = blockIdx.x * blockDim.x + threadIdx.x;
    if (i < N_EDGES / 4) {
        int4 v = reinterpret_cast<const int4*>(col)[i];
        if ((unsigned)v.x < N_NODES) g_mask[v.x] = 1;
        if ((unsigned)v.y < N_NODES) g_mask[v.y] = 1;
        if ((unsigned)v.z < N_NODES) g_mask[v.z] = 1;
        if ((unsigned)v.w < N_NODES) g_mask[v.w] = 1;
    }
}

__device__ __forceinline__ void fma2(ull& d, ull a, ull b) {
    asm("fma.rn.f32x2 %0, %1, %2, %3;" : "=l"(d) : "l"(a), "l"(b), "l"(d));
}
__device__ __forceinline__ ull pack2(float lo, float hi) {
    ull r;
    asm("mov.b64 %0, {%1, %2};" : "=l"(r) : "f"(lo), "f"(hi));
    return r;
}
__device__ __forceinline__ void unpack2(float& lo, float& hi, ull v) {
    asm("mov.b64 {%0, %1}, %2;" : "=f"(lo), "=f"(hi) : "l"(v));
}

// C[n,:] = mask[n] ? A[n,:] @ B : 0, and clear mask[n].
__global__ __launch_bounds__(NT, 2) void gat_gemm_kernel(
    const float* __restrict__ A, const float* __restrict__ B,
    float* __restrict__ C)
{
    __shared__ float As[BK][BM + 4];
    __shared__ float Bs[BK][BN];
    __shared__ float smask[BM];

    const int tid = threadIdx.x;
    const int tx = tid & 15;    // column group (8 wide)
    const int ty = tid >> 4;    // row group (8 tall)
    const int row0 = blockIdx.x * BM;

    // Load + self-clear indegree mask (one thread per row => no race).
    if (tid < BM) {
        int r = row0 + tid;
        unsigned char m = 0;
        if (r < N_NODES) { m = g_mask[r]; g_mask[r] = 0; }
        smask[tid] = m ? 1.0f : 0.0f;
    }

    ull acc2[4][8];   // acc2[p][j] = (C[2p][j], C[2p+1][j]) packed f32x2
#pragma unroll
    for (int p = 0; p < 4; p++)
#pragma unroll
        for (int j = 0; j < 8; j++) acc2[p][j] = 0ull;

    for (int kk = 0; kk < IN_CH; kk += BK) {
        // ---- A tile (BM x BK) -> As[k][m] transposed. 1024 float4, 4/thread.
#pragma unroll
        for (int l = 0; l < 4; l++) {
            int idx = tid + l * NT;
            int r   = idx >> 3;          // 0..127
            int c4  = idx & 7;           // 0..7 (float4 within 32-wide k slice)
            int gr  = row0 + r;
            float4 v = make_float4(0.f, 0.f, 0.f, 0.f);
            if (gr < N_NODES)
                v = *reinterpret_cast<const float4*>(&A[(long)gr * IN_CH + kk + c4 * 4]);
            As[c4 * 4 + 0][r] = v.x;
            As[c4 * 4 + 1][r] = v.y;
            As[c4 * 4 + 2][r] = v.z;
            As[c4 * 4 + 3][r] = v.w;
        }
        // ---- B tile (BK x BN). 1024 float4, 4/thread.
#pragma unroll
        for (int l = 0; l < 4; l++) {
            int idx = tid + l * NT;
            int r   = idx >> 5;          // 0..31
            int c4  = idx & 31;          // 0..31
            float4 v = *reinterpret_cast<const float4*>(&B[(kk + r) * OUT_TOT + c4 * 4]);
            *reinterpret_cast<float4*>(&Bs[r][c4 * 4]) = v;
        }
        __syncthreads();

#pragma unroll 8
        for (int k = 0; k < BK; k++) {
            // a: 4 packed row-pairs, natural 8B loads from shared
            ull a2[4];
#pragma unroll
            for (int p = 0; p < 4; p++)
                a2[p] = *reinterpret_cast<const ull*>(&As[k][ty * 8 + 2 * p]);
            // b: 8 broadcast pairs
            float4 u0 = *reinterpret_cast<const float4*>(&Bs[k][tx * 8]);
            float4 u1 = *reinterpret_cast<const float4*>(&Bs[k][tx * 8 + 4]);
            ull bb[8];
            bb[0] = pack2(u0.x, u0.x); bb[1] = pack2(u0.y, u0.y);
            bb[2] = pack2(u0.z, u0.z); bb[3] = pack2(u0.w, u0.w);
            bb[4] = pack2(u1.x, u1.x); bb[5] = pack2(u1.y, u1.y);
            bb[6] = pack2(u1.z, u1.z); bb[7] = pack2(u1.w, u1.w);
#pragma unroll
            for (int p = 0; p < 4; p++)
#pragma unroll
                for (int j = 0; j < 8; j++)
                    fma2(acc2[p][j], a2[p], bb[j]);
        }
        __syncthreads();
    }

    // ---- Epilogue: apply mask, vectorized stores ----
#pragma unroll
    for (int p = 0; p < 4; p++) {
        int i0 = ty * 8 + 2 * p;
#pragma unroll
        for (int half = 0; half < 2; half++) {
            int r = row0 + i0 + half;
            if (r < N_NODES) {
                float m = smask[i0 + half];
                float c[8];
#pragma unroll
                for (int j = 0; j < 8; j++) {
                    float lo, hi;
                    unpack2(lo, hi, acc2[p][j]);
                    c[j] = (half == 0 ? lo : hi) * m;
                }
                float* cp = &C[(long)r * OUT_TOT + tx * 8];
                *reinterpret_cast<float4*>(cp)     = make_float4(c[0], c[1], c[2], c[3]);
                *reinterpret_cast<float4*>(cp + 4) = make_float4(c[4], c[5], c[6], c[7]);
            }
        }
    }
}

extern "C" void kernel_launch(void* const* d_in, const int* in_sizes, int n_in,
                              void* d_out, int out_size)
{
    const float* x = (const float*)d_in[0];          // [100000, 128]
    const float* w = (const float*)d_in[1];          // [128, 128]
    // d_in[2] = att — softmax weights sum to 1 per destination segment and
    // multiply that segment's own features => mathematically irrelevant.
    const int* edge_index = (const int*)d_in[3];     // [2, 1600000] int32
    const int* col = edge_index + N_EDGES;           // edge_index[1]
    float* out = (float*)d_out;                      // [100000, 128]

    mask_scatter_kernel<<<(N_EDGES / 4 + 255) / 256, 256>>>(col);
    gat_gemm_kernel<<<(N_NODES + BM - 1) / BM, NT>>>(x, w, out);
}

// round 9
// speedup vs baseline: 1.1607x; 1.1607x over previous
#include <cuda_runtime.h>
#include <cuda_bf16.h>
#include <cstdint>

#define N_NODES 100000
#define IN_CH   128
#define OUT_TOT 128
#define N_EDGES 1600000
#define N_MASKW 3125          // 100000/32 exactly

#define BM 128
#define NT 256
#define RS 136                // smem row stride in bf16 elems (272B, LDSM conflict-free)

// SMEM layout (dynamic)
#define SM_MASK 0             // 4 x u32
#define SM_AH   32
#define SM_AL   (SM_AH + 128 * RS * 2)     // +34816
#define SM_BH   (SM_AL + 128 * RS * 2)
#define SM_BL   (SM_BH + 128 * RS * 2)
#define SM_TOTAL (SM_BL + 128 * RS * 2)    // 139296 bytes

// Per-node indegree bitmask. Zero at module load; GEMM epilogue re-clears
// its own words every launch => graph-replay deterministic.
__device__ unsigned g_maskw[N_MASKW];

// ---------------- mask scatter: SMEM bitmask then L2 merge ----------------
__global__ __launch_bounds__(NT) void mask_scatter_kernel(const int* __restrict__ col) {
    __shared__ unsigned s_bits[N_MASKW];
    int tid = threadIdx.x;
    for (int i = tid; i < N_MASKW; i += NT) s_bits[i] = 0u;
    __syncthreads();

    int per = (N_EDGES + gridDim.x - 1) / gridDim.x;
    int start = blockIdx.x * per;
    int end = start + per; if (end > N_EDGES) end = N_EDGES;
    for (int i = start + tid; i < end; i += NT) {
        unsigned c = (unsigned)col[i];
        if (c < N_NODES) atomicOr(&s_bits[c >> 5], 1u << (c & 31));
    }
    __syncthreads();
    for (int i = tid; i < N_MASKW; i += NT) {
        unsigned w = s_bits[i];
        if (w) atomicOr(&g_maskw[i], w);
    }
}

// ---------------- warp-MMA helpers (base-target PTX, no 'a' features) ----------------
__device__ __forceinline__ uint32_t smem_u32(const void* p) {
    uint32_t a;
    asm("{ .reg .u64 t; cvta.to.shared.u64 t, %1; cvt.u32.u64 %0, t; }" : "=r"(a) : "l"(p));
    return a;
}
__device__ __forceinline__ void ldsm_x4(uint32_t (&r)[4], uint32_t addr) {
    asm volatile("ldmatrix.sync.aligned.m8n8.x4.shared.b16 {%0,%1,%2,%3}, [%4];"
                 : "=r"(r[0]), "=r"(r[1]), "=r"(r[2]), "=r"(r[3]) : "r"(addr));
}
__device__ __forceinline__ void ldsm_x4_t(uint32_t (&r)[4], uint32_t addr) {
    asm volatile("ldmatrix.sync.aligned.m8n8.x4.trans.shared.b16 {%0,%1,%2,%3}, [%4];"
                 : "=r"(r[0]), "=r"(r[1]), "=r"(r[2]), "=r"(r[3]) : "r"(addr));
}
__device__ __forceinline__ void mma_bf16(float (&d)[4], const uint32_t (&a)[4],
                                         uint32_t b0, uint32_t b1) {
    asm volatile(
        "mma.sync.aligned.m16n8k16.row.col.f32.bf16.bf16.f32 "
        "{%0,%1,%2,%3}, {%4,%5,%6,%7}, {%8,%9}, {%0,%1,%2,%3};"
        : "+f"(d[0]), "+f"(d[1]), "+f"(d[2]), "+f"(d[3])
        : "r"(a[0]), "r"(a[1]), "r"(a[2]), "r"(a[3]), "r"(b0), "r"(b1));
}

__device__ __forceinline__ void split1(float x, unsigned short& h, unsigned short& l) {
    __nv_bfloat16 bh = __float2bfloat16(x);
    float r = x - __bfloat162float(bh);
    __nv_bfloat16 bl = __float2bfloat16(r);
    h = __bfloat16_as_ushort(bh);
    l = __bfloat16_as_ushort(bl);
}
__device__ __forceinline__ uint2 split4(float4 v) {
    unsigned short h0, h1, h2, h3, l0, l1, l2, l3;
    split1(v.x, h0, l0); split1(v.y, h1, l1);
    split1(v.z, h2, l2); split1(v.w, h3, l3);
    // returns nothing useful alone; helper kept inline below instead
    return make_uint2(0, 0);
}

// ---------------- GEMM: C[n,:] = mask[n] ? A[n,:] @ B : 0 ----------------
// A: [N_NODES,128] fp32, B: [128,128] fp32 row-major, C: [N_NODES,128] fp32.
// bf16 3-product split executed on HMMA (mma.sync).
__global__ __launch_bounds__(NT) void gat_gemm_mma(
    const float* __restrict__ A, const float* __restrict__ B, float* __restrict__ C)
{
    extern __shared__ char smem[];
    const uint32_t sb = smem_u32(smem);
    const int tid = threadIdx.x;
    const int lane = tid & 31;
    const int wid = tid >> 5;
    const int row0 = blockIdx.x * BM;

    // read + self-clear the 4 mask words this CTA owns (disjoint across CTAs)
    if (tid < 4) {
        int w = (row0 >> 5) + tid;
        unsigned mw = 0;
        if (w < N_MASKW) { mw = g_maskw[w]; g_maskw[w] = 0u; }
        reinterpret_cast<unsigned*>(smem + SM_MASK)[tid] = mw;
    }

    // ---- Convert A tile (128x128 fp32 -> bf16 hi/lo), row-major stride RS ----
#pragma unroll
    for (int i = 0; i < 16; i++) {
        int idx = tid + i * NT;          // 0..4095
        int m  = idx >> 5;               // 0..127
        int k0 = (idx & 31) * 4;
        float4 v = make_float4(0.f, 0.f, 0.f, 0.f);
        int gr = row0 + m;
        if (gr < N_NODES)
            v = *reinterpret_cast<const float4*>(A + (size_t)gr * IN_CH + k0);
        unsigned short h0, h1, h2, h3, l0, l1, l2, l3;
        split1(v.x, h0, l0); split1(v.y, h1, l1);
        split1(v.z, h2, l2); split1(v.w, h3, l3);
        uint2 hh = make_uint2((unsigned)h0 | ((unsigned)h1 << 16),
                              (unsigned)h2 | ((unsigned)h3 << 16));
        uint2 ll = make_uint2((unsigned)l0 | ((unsigned)l1 << 16),
                              (unsigned)l2 | ((unsigned)l3 << 16));
        int off = (m * RS + k0) * 2;
        *reinterpret_cast<uint2*>(smem + SM_AH + off) = hh;
        *reinterpret_cast<uint2*>(smem + SM_AL + off) = ll;
    }
    // ---- Convert B (gmem [K=128, N=128] row-major -> bf16 hi/lo, same layout) ----
#pragma unroll
    for (int i = 0; i < 16; i++) {
        int idx = tid + i * NT;
        int k  = idx >> 5;
        int n0 = (idx & 31) * 4;
        float4 v = *reinterpret_cast<const float4*>(B + (size_t)k * OUT_TOT + n0);
        unsigned short h0, h1, h2, h3, l0, l1, l2, l3;
        split1(v.x, h0, l0); split1(v.y, h1, l1);
        split1(v.z, h2, l2); split1(v.w, h3, l3);
        uint2 hh = make_uint2((unsigned)h0 | ((unsigned)h1 << 16),
                              (unsigned)h2 | ((unsigned)h3 << 16));
        uint2 ll = make_uint2((unsigned)l0 | ((unsigned)l1 << 16),
                              (unsigned)l2 | ((unsigned)l3 << 16));
        int off = (k * RS + n0) * 2;
        *reinterpret_cast<uint2*>(smem + SM_BH + off) = hh;
        *reinterpret_cast<uint2*>(smem + SM_BL + off) = ll;
    }
    __syncthreads();

    // ---- Warp tiling: 4(M) x 2(N) warps; warp tile 32x64 ----
    const int wm = wid & 3;          // 0..3
    const int wn = wid >> 2;         // 0..1
    const int rbase = wm * 32;
    const int cbase = wn * 64;

    // per-thread ldmatrix base offsets (elems); +mi*16*RS / +ks*16 for A;
    // +ks*16*RS / +nj*16 for B
    const uint32_t aoff = (uint32_t)((rbase + (lane & 15)) * RS + 8 * (lane >> 4)) * 2;
    const uint32_t boff = (uint32_t)((lane & 15) * RS + cbase + 8 * (lane >> 4)) * 2;
    const uint32_t aBaseH = sb + SM_AH + aoff, aBaseL = sb + SM_AL + aoff;
    const uint32_t bBaseH = sb + SM_BH + boff, bBaseL = sb + SM_BL + boff;

    float acc[2][8][4];
#pragma unroll
    for (int mi = 0; mi < 2; mi++)
#pragma unroll
        for (int n8 = 0; n8 < 8; n8++)
#pragma unroll
            for (int q = 0; q < 4; q++) acc[mi][n8][q] = 0.f;

#pragma unroll
    for (int p = 0; p < 3; p++) {          // AhBh, AhBl, AlBh
        const uint32_t aB = (p == 2) ? aBaseL : aBaseH;
        const uint32_t bB = (p == 1) ? bBaseL : bBaseH;
#pragma unroll
        for (int ks = 0; ks < 8; ks++) {
            uint32_t a[2][4], b[4][4];
            ldsm_x4(a[0], aB + 2 * (ks * 16));
            ldsm_x4(a[1], aB + 2 * (16 * RS + ks * 16));
#pragma unroll
            for (int nj = 0; nj < 4; nj++)
                ldsm_x4_t(b[nj], bB + 2 * (ks * 16 * RS + nj * 16));
#pragma unroll
            for (int mi = 0; mi < 2; mi++)
#pragma unroll
                for (int n8 = 0; n8 < 8; n8++)
                    mma_bf16(acc[mi][n8], a[mi],
                             b[n8 >> 1][(n8 & 1) * 2], b[n8 >> 1][(n8 & 1) * 2 + 1]);
        }
    }

    // ---- Epilogue (per-warp, register accumulators; no barrier needed) ----
    const unsigned* mw = reinterpret_cast<const unsigned*>(smem + SM_MASK);
    const int group = lane >> 2;
    const int tc = lane & 3;
#pragma unroll
    for (int mi = 0; mi < 2; mi++) {
#pragma unroll
        for (int half = 0; half < 2; half++) {
            int rloc = rbase + mi * 16 + group + half * 8;   // 0..127
            int r = row0 + rloc;
            float mv = ((mw[rloc >> 5] >> (rloc & 31)) & 1u) ? 1.0f : 0.0f;
            if (r < N_NODES) {
                float* cp = C + (size_t)r * OUT_TOT + cbase + tc * 2;
#pragma unroll
                for (int n8 = 0; n8 < 8; n8++) {
                    float2 o;
                    o.x = acc[mi][n8][half * 2 + 0] * mv;
                    o.y = acc[mi][n8][half * 2 + 1] * mv;
                    *reinterpret_cast<float2*>(cp + n8 * 8) = o;
                }
            }
        }
    }
}

extern "C" void kernel_launch(void* const* d_in, const int* in_sizes, int n_in,
                              void* d_out, int out_size)
{
    const float* x = (const float*)d_in[0];          // [100000, 128]
    const float* w = (const float*)d_in[1];          // [128, 128]
    // d_in[2] = att — softmax weights sum to 1 per destination segment and
    // multiply that segment's own features => mathematically irrelevant.
    const int* edge_index = (const int*)d_in[3];     // [2, 1600000] int32
    const int* col = edge_index + N_EDGES;           // edge_index[1]
    float* out = (float*)d_out;

    static bool attr_set = false;
    if (!attr_set) {
        cudaFuncSetAttribute(gat_gemm_mma,
                             cudaFuncAttributeMaxDynamicSharedMemorySize, SM_TOTAL);
        attr_set = true;
    }

    mask_scatter_kernel<<<148, NT>>>(col);
    gat_gemm_mma<<<(N_NODES + BM - 1) / BM, NT, SM_TOTAL>>>(x, w, out);
}

// round 10
// speedup vs baseline: 1.3738x; 1.1836x over previous
#include <cuda_runtime.h>
#include <cuda_bf16.h>
#include <cstdint>

#define N_NODES 100000
#define IN_CH   128
#define OUT_TOT 128
#define N_EDGES 1600000
#define N_MASKW 3125          // 100000/32 exactly

#define BM 64
#define NT 256
#define RS 136                // smem row stride in bf16 elems (272B, LDSM conflict-free)

// SMEM layout (dynamic)
#define SM_MASK 0             // 2 x u32
#define SM_AH   32
#define SM_AL   (SM_AH + BM * RS * 2)      // +17408
#define SM_BH   (SM_AL + BM * RS * 2)
#define SM_BL   (SM_BH + 128 * RS * 2)     // +34816
#define SM_TOTAL (SM_BL + 128 * RS * 2)    // 104,480 bytes -> 2 CTAs/SM

// Per-node indegree bitmask. Zero at module load; GEMM epilogue re-clears
// its own words every launch => graph-replay deterministic.
__device__ unsigned g_maskw[N_MASKW];
// Preconverted B (hi/lo bf16), written identically every launch.
__device__ __nv_bfloat16 g_Bh[128 * 128];
__device__ __nv_bfloat16 g_Bl[128 * 128];

// ---------------- helpers ----------------
__device__ __forceinline__ uint32_t smem_u32(const void* p) {
    uint32_t a;
    asm("{ .reg .u64 t; cvta.to.shared.u64 t, %1; cvt.u32.u64 %0, t; }" : "=r"(a) : "l"(p));
    return a;
}
__device__ __forceinline__ void ldsm_x4(uint32_t (&r)[4], uint32_t addr) {
    asm volatile("ldmatrix.sync.aligned.m8n8.x4.shared.b16 {%0,%1,%2,%3}, [%4];"
                 : "=r"(r[0]), "=r"(r[1]), "=r"(r[2]), "=r"(r[3]) : "r"(addr));
}
__device__ __forceinline__ void ldsm_x4_t(uint32_t (&r)[4], uint32_t addr) {
    asm volatile("ldmatrix.sync.aligned.m8n8.x4.trans.shared.b16 {%0,%1,%2,%3}, [%4];"
                 : "=r"(r[0]), "=r"(r[1]), "=r"(r[2]), "=r"(r[3]) : "r"(addr));
}
__device__ __forceinline__ void mma_bf16(float (&d)[4], const uint32_t (&a)[4],
                                         uint32_t b0, uint32_t b1) {
    asm volatile(
        "mma.sync.aligned.m16n8k16.row.col.f32.bf16.bf16.f32 "
        "{%0,%1,%2,%3}, {%4,%5,%6,%7}, {%8,%9}, {%0,%1,%2,%3};"
        : "+f"(d[0]), "+f"(d[1]), "+f"(d[2]), "+f"(d[3])
        : "r"(a[0]), "r"(a[1]), "r"(a[2]), "r"(a[3]), "r"(b0), "r"(b1));
}
__device__ __forceinline__ void split1(float x, unsigned short& h, unsigned short& l) {
    __nv_bfloat16 bh = __float2bfloat16(x);
    float r = x - __bfloat162float(bh);
    __nv_bfloat16 bl = __float2bfloat16(r);
    h = __bfloat16_as_ushort(bh);
    l = __bfloat16_as_ushort(bl);
}

// ---------------- B preconvert (once per launch, 16K elems) ----------------
__global__ __launch_bounds__(NT) void convert_b_kernel(const float* __restrict__ B) {
    int i = blockIdx.x * NT + threadIdx.x;   // grid 64 -> 16384 threads
    float v = B[i];
    unsigned short h, l;
    split1(v, h, l);
    g_Bh[i] = __ushort_as_bfloat16(h);
    g_Bl[i] = __ushort_as_bfloat16(l);
}

// ---------------- mask scatter: SMEM bitmask then L2 merge ----------------
__global__ __launch_bounds__(NT) void mask_scatter_kernel(const int* __restrict__ col) {
    __shared__ unsigned s_bits[N_MASKW];
    int tid = threadIdx.x;
    for (int i = tid; i < N_MASKW; i += NT) s_bits[i] = 0u;
    __syncthreads();

    int per = (N_EDGES + gridDim.x - 1) / gridDim.x;
    int start = blockIdx.x * per;
    int end = start + per; if (end > N_EDGES) end = N_EDGES;
    for (int i = start + tid; i < end; i += NT) {
        unsigned c = (unsigned)col[i];
        if (c < N_NODES) atomicOr(&s_bits[c >> 5], 1u << (c & 31));
    }
    __syncthreads();
    for (int i = tid; i < N_MASKW; i += NT) {
        unsigned w = s_bits[i];
        if (w) atomicOr(&g_maskw[i], w);
    }
}

// ---------------- GEMM: C[n,:] = mask[n] ? A[n,:] @ B : 0 ----------------
__global__ __launch_bounds__(NT, 2) void gat_gemm_mma(
    const float* __restrict__ A, float* __restrict__ C)
{
    extern __shared__ char smem[];
    const uint32_t sb = smem_u32(smem);
    const int tid = threadIdx.x;
    const int lane = tid & 31;
    const int wid = tid >> 5;
    const int row0 = blockIdx.x * BM;

    // read + self-clear the 2 mask words this CTA owns (disjoint across CTAs)
    if (tid < 2) {
        int w = (row0 >> 5) + tid;
        unsigned mw = 0;
        if (w < N_MASKW) { mw = g_maskw[w]; g_maskw[w] = 0u; }
        reinterpret_cast<unsigned*>(smem + SM_MASK)[tid] = mw;
    }

    // ---- A tile (64x128 fp32 -> bf16 hi/lo in smem) ----
#pragma unroll
    for (int i = 0; i < 8; i++) {
        int idx = tid + i * NT;          // 0..2047
        int m  = idx >> 5;               // 0..63
        int k0 = (idx & 31) * 4;
        float4 v = make_float4(0.f, 0.f, 0.f, 0.f);
        int gr = row0 + m;
        if (gr < N_NODES)
            v = *reinterpret_cast<const float4*>(A + (size_t)gr * IN_CH + k0);
        unsigned short h0, h1, h2, h3, l0, l1, l2, l3;
        split1(v.x, h0, l0); split1(v.y, h1, l1);
        split1(v.z, h2, l2); split1(v.w, h3, l3);
        uint2 hh = make_uint2((unsigned)h0 | ((unsigned)h1 << 16),
                              (unsigned)h2 | ((unsigned)h3 << 16));
        uint2 ll = make_uint2((unsigned)l0 | ((unsigned)l1 << 16),
                              (unsigned)l2 | ((unsigned)l3 << 16));
        int off = (m * RS + k0) * 2;
        *reinterpret_cast<uint2*>(smem + SM_AH + off) = hh;
        *reinterpret_cast<uint2*>(smem + SM_AL + off) = ll;
    }
    // ---- B tiles: straight bf16 copy from preconverted globals ----
#pragma unroll
    for (int i = 0; i < 8; i++) {
        int idx = tid + i * NT;          // 0..2047
        int k  = idx >> 4;               // 0..127
        int n0 = (idx & 15) * 8;         // 0..120, 8 bf16 = 16B
        int soff = (k * RS + n0) * 2;
        *reinterpret_cast<uint4*>(smem + SM_BH + soff) =
            *reinterpret_cast<const uint4*>(&g_Bh[k * OUT_TOT + n0]);
        *reinterpret_cast<uint4*>(smem + SM_BL + soff) =
            *reinterpret_cast<const uint4*>(&g_Bl[k * OUT_TOT + n0]);
    }
    __syncthreads();

    // ---- Warp tiling: 2(M) x 4(N); warp tile 32x32 ----
    const int wm = wid & 1;
    const int wn = wid >> 1;         // 0..3
    const int rbase = wm * 32;
    const int cbase = wn * 32;

    const uint32_t aoff = (uint32_t)((rbase + (lane & 15)) * RS + 8 * (lane >> 4)) * 2;
    const uint32_t boff = (uint32_t)((lane & 15) * RS + cbase + 8 * (lane >> 4)) * 2;
    const uint32_t aBaseH = sb + SM_AH + aoff, aBaseL = sb + SM_AL + aoff;
    const uint32_t bBaseH = sb + SM_BH + boff, bBaseL = sb + SM_BL + boff;

    float acc[2][4][4];
#pragma unroll
    for (int mi = 0; mi < 2; mi++)
#pragma unroll
        for (int n8 = 0; n8 < 4; n8++)
#pragma unroll
            for (int q = 0; q < 4; q++) acc[mi][n8][q] = 0.f;

#pragma unroll
    for (int p = 0; p < 3; p++) {          // AhBh, AhBl, AlBh
        const uint32_t aB = (p == 2) ? aBaseL : aBaseH;
        const uint32_t bB = (p == 1) ? bBaseL : bBaseH;
#pragma unroll
        for (int ks = 0; ks < 8; ks++) {
            uint32_t a[2][4], b[2][4];
            ldsm_x4(a[0], aB + 2 * (ks * 16));
            ldsm_x4(a[1], aB + 2 * (16 * RS + ks * 16));
            ldsm_x4_t(b[0], bB + 2 * (ks * 16 * RS));
            ldsm_x4_t(b[1], bB + 2 * (ks * 16 * RS + 16));
#pragma unroll
            for (int mi = 0; mi < 2; mi++)
#pragma unroll
                for (int n8 = 0; n8 < 4; n8++)
                    mma_bf16(acc[mi][n8], a[mi],
                             b[n8 >> 1][(n8 & 1) * 2], b[n8 >> 1][(n8 & 1) * 2 + 1]);
        }
    }

    // ---- Epilogue (register accumulators; no barrier needed) ----
    const unsigned* mw = reinterpret_cast<const unsigned*>(smem + SM_MASK);
    const int group = lane >> 2;
    const int tc = lane & 3;
#pragma unroll
    for (int mi = 0; mi < 2; mi++) {
#pragma unroll
        for (int half = 0; half < 2; half++) {
            int rloc = rbase + mi * 16 + group + half * 8;   // 0..63
            int r = row0 + rloc;
            float mv = ((mw[rloc >> 5] >> (rloc & 31)) & 1u) ? 1.0f : 0.0f;
            if (r < N_NODES) {
                float* cp = C + (size_t)r * OUT_TOT + cbase + tc * 2;
#pragma unroll
                for (int n8 = 0; n8 < 4; n8++) {
                    float2 o;
                    o.x = acc[mi][n8][half * 2 + 0] * mv;
                    o.y = acc[mi][n8][half * 2 + 1] * mv;
                    *reinterpret_cast<float2*>(cp + n8 * 8) = o;
                }
            }
        }
    }
}

extern "C" void kernel_launch(void* const* d_in, const int* in_sizes, int n_in,
                              void* d_out, int out_size)
{
    const float* x = (const float*)d_in[0];          // [100000, 128]
    const float* w = (const float*)d_in[1];          // [128, 128]
    // d_in[2] = att — softmax weights sum to 1 per destination segment and
    // multiply that segment's own features => mathematically irrelevant.
    const int* edge_index = (const int*)d_in[3];     // [2, 1600000] int32
    const int* col = edge_index + N_EDGES;           // edge_index[1]
    float* out = (float*)d_out;

    static bool attr_set = false;
    if (!attr_set) {
        cudaFuncSetAttribute(gat_gemm_mma,
                             cudaFuncAttributeMaxDynamicSharedMemorySize, SM_TOTAL);
        attr_set = true;
    }

    convert_b_kernel<<<(128 * 128) / NT, NT>>>(w);
    mask_scatter_kernel<<<148, NT>>>(col);
    gat_gemm_mma<<<(N_NODES + BM - 1) / BM, NT, SM_TOTAL>>>(x, out);
}

// round 11
// speedup vs baseline: 1.4547x; 1.0589x over previous
#include <cuda_runtime.h>
#include <cuda_bf16.h>
#include <cstdint>

#define N_NODES 100000
#define IN_CH   128
#define OUT_TOT 128
#define N_EDGES 1600000
#define N_MASKW 3125          // 100000/32 exactly

#define BM 64
#define NT 256
#define RS 136                // smem row stride in bf16 elems (272B, LDSM conflict-free)
#define N_TILES ((N_NODES + BM - 1) / BM)   // 1563
#define GRID_P 296            // persistent CTAs: 2 per SM x 148

// SMEM layout (dynamic)
#define SM_MASK 0             // 2 x u32
#define SM_AH   32
#define SM_AL   (SM_AH + BM * RS * 2)      // +17408
#define SM_BH   (SM_AL + BM * RS * 2)
#define SM_BL   (SM_BH + 128 * RS * 2)     // +34816
#define SM_TOTAL (SM_BL + 128 * RS * 2)    // 104,480 bytes -> 2 CTAs/SM

// Per-node indegree bitmask. Zero at module load; GEMM epilogue re-clears
// its own words every launch => graph-replay deterministic.
__device__ unsigned g_maskw[N_MASKW];
// Preconverted B (hi/lo bf16), rewritten identically every launch (scatter kernel).
__device__ __nv_bfloat16 g_Bh[128 * 128];
__device__ __nv_bfloat16 g_Bl[128 * 128];

// ---------------- helpers ----------------
__device__ __forceinline__ uint32_t smem_u32(const void* p) {
    uint32_t a;
    asm("{ .reg .u64 t; cvta.to.shared.u64 t, %1; cvt.u32.u64 %0, t; }" : "=r"(a) : "l"(p));
    return a;
}
__device__ __forceinline__ void ldsm_x4(uint32_t (&r)[4], uint32_t addr) {
    asm volatile("ldmatrix.sync.aligned.m8n8.x4.shared.b16 {%0,%1,%2,%3}, [%4];"
                 : "=r"(r[0]), "=r"(r[1]), "=r"(r[2]), "=r"(r[3]) : "r"(addr));
}
__device__ __forceinline__ void ldsm_x4_t(uint32_t (&r)[4], uint32_t addr) {
    asm volatile("ldmatrix.sync.aligned.m8n8.x4.trans.shared.b16 {%0,%1,%2,%3}, [%4];"
                 : "=r"(r[0]), "=r"(r[1]), "=r"(r[2]), "=r"(r[3]) : "r"(addr));
}
__device__ __forceinline__ void mma_bf16(float (&d)[4], const uint32_t (&a)[4],
                                         uint32_t b0, uint32_t b1) {
    asm volatile(
        "mma.sync.aligned.m16n8k16.row.col.f32.bf16.bf16.f32 "
        "{%0,%1,%2,%3}, {%4,%5,%6,%7}, {%8,%9}, {%0,%1,%2,%3};"
        : "+f"(d[0]), "+f"(d[1]), "+f"(d[2]), "+f"(d[3])
        : "r"(a[0]), "r"(a[1]), "r"(a[2]), "r"(a[3]), "r"(b0), "r"(b1));
}
__device__ __forceinline__ void split1(float x, unsigned short& h, unsigned short& l) {
    __nv_bfloat16 bh = __float2bfloat16(x);
    float r = x - __bfloat162float(bh);
    __nv_bfloat16 bl = __float2bfloat16(r);
    h = __bfloat16_as_ushort(bh);
    l = __bfloat16_as_ushort(bl);
}

// ------- mask scatter (SMEM bitmask -> L2 merge) + B split preconvert -------
__global__ __launch_bounds__(NT) void mask_scatter_kernel(const int* __restrict__ col,
                                                          const float* __restrict__ B) {
    __shared__ unsigned s_bits[N_MASKW];
    int tid = threadIdx.x;

    // B conversion folded in: 16384 elems over 148*256 threads -> <=1 per thread
    int gi = blockIdx.x * NT + tid;
    if (gi < 128 * 128) {
        unsigned short h, l;
        split1(B[gi], h, l);
        g_Bh[gi] = __ushort_as_bfloat16(h);
        g_Bl[gi] = __ushort_as_bfloat16(l);
    }

    for (int i = tid; i < N_MASKW; i += NT) s_bits[i] = 0u;
    __syncthreads();

    int per = (N_EDGES + gridDim.x - 1) / gridDim.x;
    int start = blockIdx.x * per;
    int end = start + per; if (end > N_EDGES) end = N_EDGES;
    for (int i = start + tid; i < end; i += NT) {
        unsigned c = (unsigned)col[i];
        if (c < N_NODES) atomicOr(&s_bits[c >> 5], 1u << (c & 31));
    }
    __syncthreads();
    for (int i = tid; i < N_MASKW; i += NT) {
        unsigned w = s_bits[i];
        if (w) atomicOr(&g_maskw[i], w);
    }
}

// ---------------- persistent GEMM: C[n,:] = mask[n] ? A[n,:] @ B : 0 ----------------
__global__ __launch_bounds__(NT, 2) void gat_gemm_mma(
    const float* __restrict__ A, float* __restrict__ C)
{
    extern __shared__ char smem[];
    const uint32_t sb = smem_u32(smem);
    const int tid = threadIdx.x;
    const int lane = tid & 31;
    const int wid = tid >> 5;

    // ---- B tiles into SMEM once per CTA (bf16, preconverted) ----
#pragma unroll
    for (int i = 0; i < 8; i++) {
        int idx = tid + i * NT;          // 0..2047
        int k  = idx >> 4;               // 0..127
        int n0 = (idx & 15) * 8;         // 8 bf16 = 16B
        int soff = (k * RS + n0) * 2;
        *reinterpret_cast<uint4*>(smem + SM_BH + soff) =
            *reinterpret_cast<const uint4*>(&g_Bh[k * OUT_TOT + n0]);
        *reinterpret_cast<uint4*>(smem + SM_BL + soff) =
            *reinterpret_cast<const uint4*>(&g_Bl[k * OUT_TOT + n0]);
    }

    // ---- Warp tiling: 2(M) x 4(N); warp tile 32x32 ----
    const int wm = wid & 1;
    const int wn = wid >> 1;         // 0..3
    const int rbase = wm * 32;
    const int cbase = wn * 32;
    const uint32_t aoff = (uint32_t)((rbase + (lane & 15)) * RS + 8 * (lane >> 4)) * 2;
    const uint32_t boff = (uint32_t)((lane & 15) * RS + cbase + 8 * (lane >> 4)) * 2;
    const uint32_t aBaseH = sb + SM_AH + aoff, aBaseL = sb + SM_AL + aoff;
    const uint32_t bBaseH = sb + SM_BH + boff, bBaseL = sb + SM_BL + boff;
    const unsigned* mw = reinterpret_cast<const unsigned*>(smem + SM_MASK);
    const int group = lane >> 2;
    const int tc = lane & 3;

    for (int tile = blockIdx.x; tile < N_TILES; tile += GRID_P) {
        const int row0 = tile * BM;

        // mask words for this tile (unique owner => safe self-clear)
        if (tid < 2) {
            int w = (row0 >> 5) + tid;
            unsigned m = 0;
            if (w < N_MASKW) { m = g_maskw[w]; g_maskw[w] = 0u; }
            reinterpret_cast<unsigned*>(smem + SM_MASK)[tid] = m;
        }

        // ---- A tile (64x128 fp32 -> bf16 hi/lo in smem) ----
#pragma unroll
        for (int i = 0; i < 8; i++) {
            int idx = tid + i * NT;          // 0..2047
            int m  = idx >> 5;               // 0..63
            int k0 = (idx & 31) * 4;
            float4 v = make_float4(0.f, 0.f, 0.f, 0.f);
            int gr = row0 + m;
            if (gr < N_NODES)
                v = *reinterpret_cast<const float4*>(A + (size_t)gr * IN_CH + k0);
            unsigned short h0, h1, h2, h3, l0, l1, l2, l3;
            split1(v.x, h0, l0); split1(v.y, h1, l1);
            split1(v.z, h2, l2); split1(v.w, h3, l3);
            uint2 hh = make_uint2((unsigned)h0 | ((unsigned)h1 << 16),
                                  (unsigned)h2 | ((unsigned)h3 << 16));
            uint2 ll = make_uint2((unsigned)l0 | ((unsigned)l1 << 16),
                                  (unsigned)l2 | ((unsigned)l3 << 16));
            int off = (m * RS + k0) * 2;
            *reinterpret_cast<uint2*>(smem + SM_AH + off) = hh;
            *reinterpret_cast<uint2*>(smem + SM_AL + off) = ll;
        }
        __syncthreads();   // A (and, first iter, B) visible to all warps

        float acc[2][4][4];
#pragma unroll
        for (int mi = 0; mi < 2; mi++)
#pragma unroll
            for (int n8 = 0; n8 < 4; n8++)
#pragma unroll
                for (int q = 0; q < 4; q++) acc[mi][n8][q] = 0.f;

#pragma unroll
        for (int p = 0; p < 3; p++) {          // AhBh, AhBl, AlBh
            const uint32_t aB = (p == 2) ? aBaseL : aBaseH;
            const uint32_t bB = (p == 1) ? bBaseL : bBaseH;
#pragma unroll
            for (int ks = 0; ks < 8; ks++) {
                uint32_t a[2][4], b[2][4];
                ldsm_x4(a[0], aB + 2 * (ks * 16));
                ldsm_x4(a[1], aB + 2 * (16 * RS + ks * 16));
                ldsm_x4_t(b[0], bB + 2 * (ks * 16 * RS));
                ldsm_x4_t(b[1], bB + 2 * (ks * 16 * RS + 16));
#pragma unroll
                for (int mi = 0; mi < 2; mi++)
#pragma unroll
                    for (int n8 = 0; n8 < 4; n8++)
                        mma_bf16(acc[mi][n8], a[mi],
                                 b[n8 >> 1][(n8 & 1) * 2], b[n8 >> 1][(n8 & 1) * 2 + 1]);
            }
        }

        // ---- Epilogue ----
#pragma unroll
        for (int mi = 0; mi < 2; mi++) {
#pragma unroll
            for (int half = 0; half < 2; half++) {
                int rloc = rbase + mi * 16 + group + half * 8;   // 0..63
                int r = row0 + rloc;
                float mv = ((mw[rloc >> 5] >> (rloc & 31)) & 1u) ? 1.0f : 0.0f;
                if (r < N_NODES) {
                    float* cp = C + (size_t)r * OUT_TOT + cbase + tc * 2;
#pragma unroll
                    for (int n8 = 0; n8 < 4; n8++) {
                        float2 o;
                        o.x = acc[mi][n8][half * 2 + 0] * mv;
                        o.y = acc[mi][n8][half * 2 + 1] * mv;
                        *reinterpret_cast<float2*>(cp + n8 * 8) = o;
                    }
                }
            }
        }
        __syncthreads();   // all reads of A smem + mask done before next tile
    }
}

extern "C" void kernel_launch(void* const* d_in, const int* in_sizes, int n_in,
                              void* d_out, int out_size)
{
    const float* x = (const float*)d_in[0];          // [100000, 128]
    const float* w = (const float*)d_in[1];          // [128, 128]
    // d_in[2] = att — softmax weights sum to 1 per destination segment and
    // multiply that segment's own features => mathematically irrelevant.
    const int* edge_index = (const int*)d_in[3];     // [2, 1600000] int32
    const int* col = edge_index + N_EDGES;           // edge_index[1]
    float* out = (float*)d_out;

    static bool attr_set = false;
    if (!attr_set) {
        cudaFuncSetAttribute(gat_gemm_mma,
                             cudaFuncAttributeMaxDynamicSharedMemorySize, SM_TOTAL);
        attr_set = true;
    }

    mask_scatter_kernel<<<148, NT>>>(col, w);
    gat_gemm_mma<<<GRID_P, NT, SM_TOTAL>>>(x, out);
}